// round 10
// baseline (speedup 1.0000x reference)
#include <cuda_runtime.h>

#define FULLMASK 0xFFFFFFFFu

#define CP_ASYNC_16(dst_u32, src_ptr) \
    asm volatile("cp.async.cg.shared.global [%0], [%1], 16;" \
                 :: "r"(dst_u32), "l"(src_ptr) : "memory")
#define CP_COMMIT() asm volatile("cp.async.commit_group;" ::: "memory")
#define CP_WAIT2()  asm volatile("cp.async.wait_group 2;" ::: "memory")

// One warp per 4096-element SEGMENT of a (b,c) row. Segments independent via
// a decayed warm-up halo (g^halo < 1e-10 => exact at fp32; clamps to row
// start / exact full-scan fallback if g ~ 1). Tile = 256 elements: lane owns
// 8 contiguous elements (two float4s).
//   per-lane 8-elem chain tail -> warp Kogge-Stone over lane tails (ratio
//   g^8) -> cross-tile carry with g^256 -> outputs reconstructed with the
//   exact serial recurrence seeded from the scan state.
// Input streaming uses a per-warp depth-3 cp.async ring in SMEM: bytes in
// flight come from the async queue (768 B/warp) instead of registers, so the
// body stays lean enough for 11 blocks/SM. Each lane consumes exactly the
// bytes it copied, so cp.async.wait_group alone orders the pipeline (no
// barriers). SMEM layout: tile's float4 2*lane -> slot[lane], float4
// 2*lane+1 -> slot[32+lane]  (stride-16B reads, conflict-free).
__global__ void __launch_bounds__(128, 11)
ema_scan_cpa_kernel(const float4* __restrict__ x4,
                    const float* __restrict__ w,
                    float4* __restrict__ out4,
                    int Cdim, int T, int nrows, int nseg)
{
    constexpr int SEG_TILES = 16;             // 16 * 256 = 4096 elems/segment
    constexpr int DEPTH = 3;
    __shared__ float4 sbuf[4][DEPTH][64];     // 12 KB per block

    const int warp = threadIdx.x >> 5;
    const int lane = threadIdx.x & 31;
    const int gw   = blockIdx.x * 4 + warp;   // global segment id
    const int row  = gw / nseg;
    const int seg  = gw - row * nseg;
    if (row >= nrows) return;

    const float g   = __ldg(&w[row % Cdim]);
    const float omg = 1.0f - g;

    const float g2   = g * g;
    const float g4   = g2 * g2;
    const float g8   = g4 * g4;               // lane-step ratio
    const float g16  = g8 * g8;
    const float g32  = g16 * g16;
    const float g64  = g32 * g32;
    const float g128 = g64 * g64;
    const float g256 = g128 * g128;           // tile-step ratio

    // g^(8*lane) by binary decomposition
    float pl = 1.0f;
    if (lane & 1)  pl *= g8;
    if (lane & 2)  pl *= g16;
    if (lane & 4)  pl *= g32;
    if (lane & 8)  pl *= g64;
    if (lane & 16) pl *= g128;

    // warm-up tiles: g^(256*wt) < 1e-10; exact fallback if g ~ 1
    int wt;
    if (g > 0.0f && g < 0.9999f)
        wt = (int)((-23.03f * (1.0f / 256.0f)) / __logf(g)) + 1;
    else
        wt = 0x3fffffff;
    const int seg_tile0 = seg * SEG_TILES;
    if (wt > seg_tile0) wt = seg_tile0;
    if (wt < 0) wt = 0;

    const float4* __restrict__ xin  = x4   + (size_t)row * (T >> 2);
    float4*       __restrict__ yout = out4 + (size_t)row * (T >> 2);

    const int tile_begin = seg_tile0 - wt;
    const int count      = wt + SEG_TILES;

    // SMEM u32 addresses for this lane's two slots in each ring buffer
    unsigned int s_lo[DEPTH], s_hi[DEPTH];
    #pragma unroll
    for (int d = 0; d < DEPTH; ++d) {
        s_lo[d] = (unsigned int)__cvta_generic_to_shared(&sbuf[warp][d][lane]);
        s_hi[d] = (unsigned int)__cvta_generic_to_shared(&sbuf[warp][d][32 + lane]);
    }

    // prime the pipeline: issue tiles 0..DEPTH-2
    #pragma unroll
    for (int d = 0; d < DEPTH - 1; ++d) {
        if (d < count) {
            const float4* src = xin + (tile_begin + d) * 64 + 2 * lane;
            CP_ASYNC_16(s_lo[d], src);
            CP_ASYNC_16(s_hi[d], src + 1);
        }
        CP_COMMIT();
    }

    float C = 0.0f;
    int base = tile_begin * 64 + 2 * lane;

    #pragma unroll 1
    for (int t = 0; t < count; ++t) {
        // issue tile t+DEPTH-1 into ring slot (t+DEPTH-1)%DEPTH
        const int tf = t + DEPTH - 1;
        if (tf < count) {
            const int d = tf % DEPTH;
            const float4* src = xin + (tile_begin + tf) * 64 + 2 * lane;
            CP_ASYNC_16(s_lo[d], src);
            CP_ASYNC_16(s_hi[d], src + 1);
        }
        CP_COMMIT();

        // tile t is complete once at most DEPTH-1 groups remain outstanding
        CP_WAIT2();
        const int db = t % DEPTH;
        const float4 a0 = sbuf[warp][db][lane];
        const float4 a1 = sbuf[warp][db][32 + lane];

        // per-lane chain tail over 8 contiguous elements
        float l = a0.x * omg;
        l = fmaf(g, l, a0.y * omg);
        l = fmaf(g, l, a0.z * omg);
        l = fmaf(g, l, a0.w * omg);
        l = fmaf(g, l, a1.x * omg);
        l = fmaf(g, l, a1.y * omg);
        l = fmaf(g, l, a1.z * omg);
        l = fmaf(g, l, a1.w * omg);

        // warp inclusive scan of lane tails, ratio g^8
        float v = l, tv;
        tv = __shfl_up_sync(FULLMASK, v, 1);  if (lane >= 1)  v = fmaf(g8,   tv, v);
        tv = __shfl_up_sync(FULLMASK, v, 2);  if (lane >= 2)  v = fmaf(g16,  tv, v);
        tv = __shfl_up_sync(FULLMASK, v, 4);  if (lane >= 4)  v = fmaf(g32,  tv, v);
        tv = __shfl_up_sync(FULLMASK, v, 8);  if (lane >= 8)  v = fmaf(g64,  tv, v);
        tv = __shfl_up_sync(FULLMASK, v, 16); if (lane >= 16) v = fmaf(g128, tv, v);

        // exclusive carry from earlier lanes
        float cL = __shfl_up_sync(FULLMASK, v, 1);
        if (lane == 0) cL = 0.0f;

        if (t >= wt) {
            // EMA state just before this lane's first element, then exact
            // serial reconstruction of the 8 outputs
            float y = fmaf(pl, C, cL);
            float4 o0, o1;
            y = fmaf(g, y, a0.x * omg);  o0.x = y;
            y = fmaf(g, y, a0.y * omg);  o0.y = y;
            y = fmaf(g, y, a0.z * omg);  o0.z = y;
            y = fmaf(g, y, a0.w * omg);  o0.w = y;
            y = fmaf(g, y, a1.x * omg);  o1.x = y;
            y = fmaf(g, y, a1.y * omg);  o1.y = y;
            y = fmaf(g, y, a1.z * omg);  o1.z = y;
            y = fmaf(g, y, a1.w * omg);  o1.w = y;
            __stcs(yout + base,     o0);
            __stcs(yout + base + 1, o1);
        }

        // cross-tile carry
        C = fmaf(g256, C, __shfl_sync(FULLMASK, v, 31));

        base += 64;
    }
}

extern "C" void kernel_launch(void* const* d_in, const int* in_sizes, int n_in,
                              void* d_out, int out_size)
{
    const float4* x4 = (const float4*)d_in[0];
    const float*  w  = (const float*)d_in[1];
    float4* out4 = (float4*)d_out;

    const int Cdim  = in_sizes[1];          // 512
    const int T     = 16384;                // fixed problem shape
    const int nrows = in_sizes[0] / T;      // B*C = 4096
    const int nseg  = T / 4096;             // 4 segments per row

    const int total_warps     = nrows * nseg;   // 16384
    const int warps_per_block = 4;
    dim3 block(32 * warps_per_block);           // 128 threads
    dim3 grid((total_warps + warps_per_block - 1) / warps_per_block);
    ema_scan_cpa_kernel<<<grid, block>>>(x4, w, out4, Cdim, T, nrows, nseg);
}

// round 11
// speedup vs baseline: 1.3963x; 1.3963x over previous
#include <cuda_runtime.h>

#define FULLMASK 0xFFFFFFFFu

// One warp per 4096-element SEGMENT of a (b,c) row. Segments independent via
// a decayed warm-up halo (g^halo < 1e-10 => exact at fp32; clamps to row
// start / exact full-scan fallback if g ~ 1). Tile = 256 elements: lane owns
// 8 contiguous elements (two float4s).
//   per-lane 8-elem chain tail -> warp Kogge-Stone over lane tails (ratio
//   g^8) -> cross-tile carry with g^256 -> outputs reconstructed with the
//   exact serial recurrence seeded from the scan state.
// R6 body (prefetch depth 1, 48 regs) with 64-thread blocks: 21 blocks/SM
// fit the register file -> 42 warps/SM theoretical, finer scheduling
// granularity than the 128-thread variant.
__global__ void __launch_bounds__(64)
ema_scan_b64_kernel(const float4* __restrict__ x4,
                    const float* __restrict__ w,
                    float4* __restrict__ out4,
                    int Cdim, int T, int nrows, int nseg)
{
    constexpr int SEG_TILES = 16;             // 16 * 256 = 4096 elems/segment
    const int warp = threadIdx.x >> 5;
    const int lane = threadIdx.x & 31;
    const int gw   = blockIdx.x * 2 + warp;   // global segment id
    const int row  = gw / nseg;
    const int seg  = gw - row * nseg;
    if (row >= nrows) return;

    const float g   = __ldg(&w[row % Cdim]);
    const float omg = 1.0f - g;

    const float g2   = g * g;
    const float g4   = g2 * g2;
    const float g8   = g4 * g4;               // lane-step ratio
    const float g16  = g8 * g8;
    const float g32  = g16 * g16;
    const float g64  = g32 * g32;
    const float g128 = g64 * g64;
    const float g256 = g128 * g128;           // tile-step ratio

    // g^(8*lane) by binary decomposition
    float pl = 1.0f;
    if (lane & 1)  pl *= g8;
    if (lane & 2)  pl *= g16;
    if (lane & 4)  pl *= g32;
    if (lane & 8)  pl *= g64;
    if (lane & 16) pl *= g128;

    // warm-up tiles: g^(256*wt) < 1e-10; exact fallback if g ~ 1
    int wt;
    if (g > 0.0f && g < 0.9999f)
        wt = (int)((-23.03f * (1.0f / 256.0f)) / __logf(g)) + 1;
    else
        wt = 0x3fffffff;
    const int seg_tile0 = seg * SEG_TILES;
    if (wt > seg_tile0) wt = seg_tile0;
    if (wt < 0) wt = 0;

    const float4* __restrict__ xin  = x4   + (size_t)row * (T >> 2);
    float4*       __restrict__ yout = out4 + (size_t)row * (T >> 2);

    const int tile_begin = seg_tile0 - wt;
    const int count      = wt + SEG_TILES;

    float C = 0.0f;

    int base = tile_begin * 64 + 2 * lane;
    float4 a0 = __ldcs(xin + base);
    float4 a1 = __ldcs(xin + base + 1);

    #pragma unroll 1
    for (int t = 0; t < count; ++t) {
        // prefetch next tile while this one is scanned
        float4 n0 = a0, n1 = a1;
        if (t + 1 < count) {
            n0 = __ldcs(xin + base + 64);
            n1 = __ldcs(xin + base + 65);
        }

        // per-lane chain tail over 8 contiguous elements
        float l = a0.x * omg;
        l = fmaf(g, l, a0.y * omg);
        l = fmaf(g, l, a0.z * omg);
        l = fmaf(g, l, a0.w * omg);
        l = fmaf(g, l, a1.x * omg);
        l = fmaf(g, l, a1.y * omg);
        l = fmaf(g, l, a1.z * omg);
        l = fmaf(g, l, a1.w * omg);

        // warp inclusive scan of lane tails, ratio g^8
        float v = l, tv;
        tv = __shfl_up_sync(FULLMASK, v, 1);  if (lane >= 1)  v = fmaf(g8,   tv, v);
        tv = __shfl_up_sync(FULLMASK, v, 2);  if (lane >= 2)  v = fmaf(g16,  tv, v);
        tv = __shfl_up_sync(FULLMASK, v, 4);  if (lane >= 4)  v = fmaf(g32,  tv, v);
        tv = __shfl_up_sync(FULLMASK, v, 8);  if (lane >= 8)  v = fmaf(g64,  tv, v);
        tv = __shfl_up_sync(FULLMASK, v, 16); if (lane >= 16) v = fmaf(g128, tv, v);

        // exclusive carry from earlier lanes
        float cL = __shfl_up_sync(FULLMASK, v, 1);
        if (lane == 0) cL = 0.0f;

        if (t >= wt) {
            // EMA state just before this lane's first element, then exact
            // serial reconstruction of the 8 outputs
            float y = fmaf(pl, C, cL);
            float4 o0, o1;
            y = fmaf(g, y, a0.x * omg);  o0.x = y;
            y = fmaf(g, y, a0.y * omg);  o0.y = y;
            y = fmaf(g, y, a0.z * omg);  o0.z = y;
            y = fmaf(g, y, a0.w * omg);  o0.w = y;
            y = fmaf(g, y, a1.x * omg);  o1.x = y;
            y = fmaf(g, y, a1.y * omg);  o1.y = y;
            y = fmaf(g, y, a1.z * omg);  o1.z = y;
            y = fmaf(g, y, a1.w * omg);  o1.w = y;
            __stcs(yout + base,     o0);
            __stcs(yout + base + 1, o1);
        }

        // cross-tile carry
        C = fmaf(g256, C, __shfl_sync(FULLMASK, v, 31));

        a0 = n0; a1 = n1;
        base += 64;
    }
}

extern "C" void kernel_launch(void* const* d_in, const int* in_sizes, int n_in,
                              void* d_out, int out_size)
{
    const float4* x4 = (const float4*)d_in[0];
    const float*  w  = (const float*)d_in[1];
    float4* out4 = (float4*)d_out;

    const int Cdim  = in_sizes[1];          // 512
    const int T     = 16384;                // fixed problem shape
    const int nrows = in_sizes[0] / T;      // B*C = 4096
    const int nseg  = T / 4096;             // 4 segments per row

    const int total_warps     = nrows * nseg;   // 16384
    const int warps_per_block = 2;
    dim3 block(32 * warps_per_block);           // 64 threads
    dim3 grid((total_warps + warps_per_block - 1) / warps_per_block);
    ema_scan_b64_kernel<<<grid, block>>>(x4, w, out4, Cdim, T, nrows, nseg);
}